// round 11
// baseline (speedup 1.0000x reference)
#include <cuda_runtime.h>
#include <cuda_bf16.h>

// MemModule: x(32,256,32,32) fp32, weight(2000,256) fp32
//   att = L1norm(hardshrink(softmax(xT @ W^T)))   -> (32,2000,32,32)
//   y   = att @ W                                  -> (32,256,32,32)
// d_out layout: [ y (8,388,608 floats) | att (65,536,000 floats) ]
// att region doubles as logit scratch.
// R11: K1 keeps R8's balanced inner loop (micro 4tok x 8m, plain Ws + pk2 —
// crossbar is the binding pipe, MOVs are free) but moves to 256-thread CTAs
// on 128tok x 64m tiles, 3 CTAs/SM = 24 warps (was 16). Logits BIT-IDENTICAL.
// Fused kernel reverted to the proven R9 version (202us).

#define NB   32
#define CC   256
#define HW   1024           // 32*32
#define TT   32768          // NB*HW tokens
#define MM   2000
#define Y_ELEMS  (NB*CC*HW) // 8388608
#define LAMBDA 0.0025f
#define EPSN   1e-12f
#define GQ    4             // m-split groups per token
#define MSEG  500           // MM / GQ
#define SEGCAP 16           // nz capacity per segment

typedef unsigned long long ull;

// ---------- packed f32x2 helpers ----------
__device__ __forceinline__ ull pk2(float lo, float hi) {
    ull r;
    asm("mov.b64 %0, {%1,%2};" : "=l"(r) : "f"(lo), "f"(hi));
    return r;
}
__device__ __forceinline__ void upk2(ull v, float& lo, float& hi) {
    asm("mov.b64 {%0,%1}, %2;" : "=f"(lo), "=f"(hi) : "l"(v));
}
__device__ __forceinline__ ull fma2(ull a, ull b, ull c) {
    ull d;
    asm("fma.rn.f32x2 %0, %1, %2, %3;" : "=l"(d) : "l"(a), "l"(b), "l"(c));
    return d;
}
__device__ __forceinline__ ull add2(ull a, ull b) {
    ull d;
    asm("add.rn.f32x2 %0, %1, %2;" : "=l"(d) : "l"(a), "l"(b));
    return d;
}

// ---------- accurate expf (~2 ulp), immune to fast-math ----------
__device__ __forceinline__ float exp_acc(float x) {
    float kf = fmaf(x, 1.44269504088896341f, 12582912.0f);
    kf = __fadd_rn(kf, -12582912.0f);
    float r = fmaf(kf, -0.693359375f, x);
    r = fmaf(kf, 2.12194440e-4f, r);
    float p =         1.9875691500e-4f;
    p = fmaf(p, r,    1.3981999507e-3f);
    p = fmaf(p, r,    8.3334519073e-3f);
    p = fmaf(p, r,    4.1665795894e-2f);
    p = fmaf(p, r,    1.6666665459e-1f);
    p = fmaf(p, r,    5.0000001201e-1f);
    float z2 = __fmul_rn(r, r);
    float y = fmaf(p, z2, r);
    y = __fadd_rn(y, 1.0f);
    int ki = (int)kf;
    return __fmul_rn(y, __int_as_float((ki + 127) << 23));
}

// ============================================================================
// K1: logits[t][m] = sum_c x_t[t][c] * w[m][c]  -> att region (n,m,hw) layout.
// 256 threads, tile 128 tok x 64 m, micro 4tok x 8m, 3 CTAs/SM (24 warps).
// Inner loop identical in structure to R8 (balanced crossbar:fma = 3:4).
// Chunk-16 fma chain per element BIT-IDENTICAL to R8/R10.
// ============================================================================
__global__ __launch_bounds__(256, 3) void gemm1_kernel(
    const float* __restrict__ x, const float* __restrict__ w,
    float* __restrict__ att)
{
    __shared__ float Xs[16][128];
    __shared__ float Ws[16][68];    // 64 m + 4 pad, [k][m] transposed

    const int tid = threadIdx.x;
    const int tx  = tid & 31;       // token group (4 toks)
    const int ty  = tid >> 5;       // m group (8 m), 0..7
    const int m0  = blockIdx.x * 64;
    const int t0  = blockIdx.y * 128;
    const int n   = t0 >> 10;
    const int hw0 = t0 & 1023;

    const float* xb = x + (size_t)n * (CC * HW) + hw0;

    // loader roles
    const int kX  = tid >> 5;           // 0..7 ; second half uses kX+8
    const int jX  = (tid & 31) << 2;
    const int mmW = tid >> 2;           // 0..63
    const int kqW = (tid & 3) << 2;
    const int rowW = m0 + mmW;

    float4 sx0, sx1, sw;
    sx0 = *(const float4*)&xb[(size_t)kX * HW + jX];
    sx1 = *(const float4*)&xb[(size_t)(kX + 8) * HW + jX];
    sw  = (rowW < MM) ? *(const float4*)&w[rowW * CC + kqW]
                      : make_float4(0.f, 0.f, 0.f, 0.f);

    ull acc[8][2];
    #pragma unroll
    for (int i = 0; i < 8; i++) { acc[i][0] = 0ull; acc[i][1] = 0ull; }

    for (int c0 = 0; c0 < CC; c0 += 16) {
        __syncthreads();
        *(float4*)&Xs[kX][jX]     = sx0;
        *(float4*)&Xs[kX + 8][jX] = sx1;
        Ws[kqW + 0][mmW] = sw.x;
        Ws[kqW + 1][mmW] = sw.y;
        Ws[kqW + 2][mmW] = sw.z;
        Ws[kqW + 3][mmW] = sw.w;
        __syncthreads();

        if (c0 + 16 < CC) {
            int c1 = c0 + 16;
            sx0 = *(const float4*)&xb[(size_t)(c1 + kX) * HW + jX];
            sx1 = *(const float4*)&xb[(size_t)(c1 + kX + 8) * HW + jX];
            if (rowW < MM) sw = *(const float4*)&w[rowW * CC + c1 + kqW];
        }

        ull cacc[8][2];
        #pragma unroll
        for (int i = 0; i < 8; i++) { cacc[i][0] = 0ull; cacc[i][1] = 0ull; }

        #pragma unroll
        for (int k = 0; k < 16; k++) {
            ulonglong2 xa = *(const ulonglong2*)&Xs[k][tx * 4];  // 4 toks
            float4 b0 = *(const float4*)&Ws[k][ty * 8];
            float4 b1 = *(const float4*)&Ws[k][ty * 8 + 4];
            float bv[8] = { b0.x, b0.y, b0.z, b0.w, b1.x, b1.y, b1.z, b1.w };
            #pragma unroll
            for (int mi = 0; mi < 8; mi++) {
                ull bb = pk2(bv[mi], bv[mi]);
                cacc[mi][0] = fma2(bb, xa.x, cacc[mi][0]);
                cacc[mi][1] = fma2(bb, xa.y, cacc[mi][1]);
            }
        }

        #pragma unroll
        for (int mi = 0; mi < 8; mi++) {
            acc[mi][0] = add2(acc[mi][0], cacc[mi][0]);
            acc[mi][1] = add2(acc[mi][1], cacc[mi][1]);
        }
    }

    // write logits: att[n][m][hw0 + tx*4 .. +4], coalesced STG.128
    float* ob = att + (size_t)n * ((size_t)MM * HW) + hw0 + tx * 4;
    #pragma unroll
    for (int mi = 0; mi < 8; mi++) {
        int row = m0 + ty * 8 + mi;
        if (row < MM) {
            float4 o;
            upk2(acc[mi][0], o.x, o.y);
            upk2(acc[mi][1], o.z, o.w);
            *(float4*)&ob[(size_t)row * HW] = o;
        }
    }
}

// ============================================================================
// K2': fused softmax + hard-shrink + L1-normalize + sparse y = att @ W.
// (R9 version verbatim — proven 202us.) 4 threads/token; block = 32 tokens
// x 4 groups; all att traffic warp-coalesced. Per-element chains preserved.
// ============================================================================
__global__ __launch_bounds__(128) void softmax_fused_kernel(
    float* __restrict__ att, const float* __restrict__ w,
    float* __restrict__ y)
{
    __shared__ double zs[GQ][32];
    __shared__ float  nzvS[GQ][32][SEGCAP];
    __shared__ int    nzmS[GQ][32][SEGCAP];
    __shared__ int    cntS[GQ][32];

    const int tid  = threadIdx.x;
    const int q    = tid >> 5;          // segment 0..3
    const int lane = tid & 31;          // token within block
    const int t    = blockIdx.x * 32 + lane;
    const int n    = t >> 10;
    const int hw   = t & 1023;
    float* a = att + (size_t)n * ((size_t)MM * HW) + hw;
    const int mlo = q * MSEG;

    // ---- pass A: partial Z over this segment ----
    double z = 0.0;
    for (int m = mlo; m < mlo + 496; m += 16) {
        float v[16];
        #pragma unroll
        for (int i = 0; i < 16; i++) v[i] = a[(size_t)(m + i) << 10];
        float e[16];
        #pragma unroll
        for (int i = 0; i < 16; i++) e[i] = exp_acc(v[i]);
        #pragma unroll
        for (int g = 0; g < 2; g++) {
            const float* eg = e + g * 8;
            float s01 = __fadd_rn(eg[0], eg[1]);
            float s23 = __fadd_rn(eg[2], eg[3]);
            float s45 = __fadd_rn(eg[4], eg[5]);
            float s67 = __fadd_rn(eg[6], eg[7]);
            float s03 = __fadd_rn(s01, s23);
            float s47 = __fadd_rn(s45, s67);
            z += (double)__fadd_rn(s03, s47);
        }
    }
    {   // remainder 4
        int m = mlo + 496;
        float v[4], e[4];
        #pragma unroll
        for (int i = 0; i < 4; i++) v[i] = a[(size_t)(m + i) << 10];
        #pragma unroll
        for (int i = 0; i < 4; i++) e[i] = exp_acc(v[i]);
        float s01 = __fadd_rn(e[0], e[1]);
        float s23 = __fadd_rn(e[2], e[3]);
        z += (double)__fadd_rn(s01, s23);
    }
    zs[q][lane] = z;
    __syncthreads();
    const double zt = ((zs[0][lane] + zs[1][lane]) + zs[2][lane]) + zs[3][lane];
    const float invZ = __fdiv_rn(1.0f, (float)zt);

    // ---- pass B: threshold, record nonzeros, zero this segment ----
    int   lm[SEGCAP];
    float lv[SEGCAP];
    int   cnt = 0;
    for (int m = mlo; m < mlo + MSEG; m += 4) {
        float v[4];
        #pragma unroll
        for (int i = 0; i < 4; i++) v[i] = a[(size_t)(m + i) << 10];
        #pragma unroll
        for (int i = 0; i < 4; i++) {
            float e = exp_acc(v[i]);
            float p = __fmul_rn(e, invZ);
            float d = __fadd_rn(p, -LAMBDA);
            float val;
            if (fabsf(d) < 2.5e-6f) {
                // near the discontinuity: decide membership in fp64
                double p64 = exp((double)v[i]) / zt;
                if (p64 > (double)LAMBDA) {
                    if (d > 0.f)
                        val = __fdiv_rn(__fmul_rn(d, p), __fadd_rn(d, EPSN));
                    else
                        val = p;
                } else {
                    val = 0.f;
                }
            } else {
                val = (d > 0.f) ? p : 0.f;
            }
            if (val != 0.f && cnt < SEGCAP) { lm[cnt] = m + i; lv[cnt] = val; cnt++; }
        }
        #pragma unroll
        for (int i = 0; i < 4; i++) a[(size_t)(m + i) << 10] = 0.f;
    }
    cntS[q][lane] = cnt;
    for (int k = 0; k < cnt; k++) {
        nzmS[q][lane][k] = lm[k];
        nzvS[q][lane][k] = lv[k];
    }
    __syncthreads();

    // ---- S over merged list (ascending m) ----
    float s = 0.f;
    #pragma unroll
    for (int qq = 0; qq < GQ; qq++) {
        int c = cntS[qq][lane];
        for (int k = 0; k < c; k++)
            s = __fadd_rn(s, nzvS[qq][lane][k]);
    }
    const float invS = __fdiv_rn(1.0f, fmaxf(s, 1e-12f));

    // ---- scatter this segment's normalized nonzeros ----
    for (int k = 0; k < cnt; k++)
        a[(size_t)lm[k] << 10] = __fmul_rn(lv[k], invS);

    // ---- y: this thread does c in [q*64, q*64+64), two blocks of 32 ----
    float* yb = y + (size_t)n * (CC * HW) + hw;
    #pragma unroll 1
    for (int cb = 0; cb < 2; cb++) {
        const int c0 = q * 64 + cb * 32;
        float accy[32];
        #pragma unroll
        for (int c = 0; c < 32; c++) accy[c] = 0.f;
        #pragma unroll 1
        for (int qq = 0; qq < GQ; qq++) {
            int c = cntS[qq][lane];
            for (int k = 0; k < c; k++) {
                float vn = __fmul_rn(nzvS[qq][lane][k], invS);
                const float4* wr4 =
                    (const float4*)(w + nzmS[qq][lane][k] * CC + c0);
                #pragma unroll
                for (int j = 0; j < 8; j++) {
                    float4 wv = wr4[j];
                    accy[j*4+0] = fmaf(vn, wv.x, accy[j*4+0]);
                    accy[j*4+1] = fmaf(vn, wv.y, accy[j*4+1]);
                    accy[j*4+2] = fmaf(vn, wv.z, accy[j*4+2]);
                    accy[j*4+3] = fmaf(vn, wv.w, accy[j*4+3]);
                }
            }
        }
        #pragma unroll
        for (int c = 0; c < 32; c++)
            yb[(size_t)(c0 + c) * HW] = accy[c];
    }
}

// ============================================================================
extern "C" void kernel_launch(void* const* d_in, const int* in_sizes, int n_in,
                              void* d_out, int out_size)
{
    const float* x = (const float*)d_in[0];   // (32,256,32,32)
    const float* w = (const float*)d_in[1];   // (2000,256)
    float* y   = (float*)d_out;               // first 8,388,608 floats
    float* att = y + Y_ELEMS;                 // next 65,536,000 floats

    dim3 g1(32, 256);                         // 64-m x 128-tok tiles
    gemm1_kernel<<<g1, 256>>>(x, w, att);

    softmax_fused_kernel<<<TT / 32, 128>>>(att, w, y);
}

// round 12
// speedup vs baseline: 1.4648x; 1.4648x over previous
#include <cuda_runtime.h>
#include <cuda_bf16.h>

// MemModule: x(32,256,32,32) fp32, weight(2000,256) fp32
//   att = L1norm(hardshrink(softmax(xT @ W^T)))   -> (32,2000,32,32)
//   y   = att @ W                                  -> (32,256,32,32)
// d_out layout: [ y (8,388,608 floats) | att (65,536,000 floats) ]
// att region doubles as logit scratch.
// R12: K1 = the proven R8 shape (512 thr, 128x128 tile, micro 4tok x 8m,
// plain Ws + pk2) upgraded to double-buffered smem with ONE barrier per
// chunk (commit -> stage -> barrier -> compute). Logits BIT-IDENTICAL.
// Fused kernel = proven R9 version (201us) verbatim.

#define NB   32
#define CC   256
#define HW   1024           // 32*32
#define TT   32768          // NB*HW tokens
#define MM   2000
#define Y_ELEMS  (NB*CC*HW) // 8388608
#define LAMBDA 0.0025f
#define EPSN   1e-12f
#define GQ    4             // m-split groups per token
#define MSEG  500           // MM / GQ
#define SEGCAP 16           // nz capacity per segment

typedef unsigned long long ull;

// ---------- packed f32x2 helpers ----------
__device__ __forceinline__ ull pk2(float lo, float hi) {
    ull r;
    asm("mov.b64 %0, {%1,%2};" : "=l"(r) : "f"(lo), "f"(hi));
    return r;
}
__device__ __forceinline__ void upk2(ull v, float& lo, float& hi) {
    asm("mov.b64 {%0,%1}, %2;" : "=f"(lo), "=f"(hi) : "l"(v));
}
__device__ __forceinline__ ull fma2(ull a, ull b, ull c) {
    ull d;
    asm("fma.rn.f32x2 %0, %1, %2, %3;" : "=l"(d) : "l"(a), "l"(b), "l"(c));
    return d;
}
__device__ __forceinline__ ull add2(ull a, ull b) {
    ull d;
    asm("add.rn.f32x2 %0, %1, %2;" : "=l"(d) : "l"(a), "l"(b));
    return d;
}

// ---------- accurate expf (~2 ulp), immune to fast-math ----------
__device__ __forceinline__ float exp_acc(float x) {
    float kf = fmaf(x, 1.44269504088896341f, 12582912.0f);
    kf = __fadd_rn(kf, -12582912.0f);
    float r = fmaf(kf, -0.693359375f, x);
    r = fmaf(kf, 2.12194440e-4f, r);
    float p =         1.9875691500e-4f;
    p = fmaf(p, r,    1.3981999507e-3f);
    p = fmaf(p, r,    8.3334519073e-3f);
    p = fmaf(p, r,    4.1665795894e-2f);
    p = fmaf(p, r,    1.6666665459e-1f);
    p = fmaf(p, r,    5.0000001201e-1f);
    float z2 = __fmul_rn(r, r);
    float y = fmaf(p, z2, r);
    y = __fadd_rn(y, 1.0f);
    int ki = (int)kf;
    return __fmul_rn(y, __int_as_float((ki + 127) << 23));
}

// ============================================================================
// K1: logits[t][m] = sum_c x_t[t][c] * w[m][c]  -> att region (n,m,hw) layout.
// 512 threads, tile 128 tok x 128 m, micro 4tok x 8m. Double-buffered smem,
// single barrier per chunk: commit(buf) -> stage next -> barrier -> compute.
// Chunk-16 fma chain per element BIT-IDENTICAL to R8.
// ============================================================================
__global__ __launch_bounds__(512) void gemm1_kernel(
    const float* __restrict__ x, const float* __restrict__ w,
    float* __restrict__ att)
{
    __shared__ float Xs[2][16][128];
    __shared__ float Ws[2][16][132];   // +4 pad, [k][m] transposed

    const int tid = threadIdx.x;
    const int tx  = tid & 31;       // token group (4 toks)
    const int ty  = tid >> 5;       // m group (8 m), 0..15
    const int m0  = blockIdx.x * 128;
    const int t0  = blockIdx.y * 128;
    const int n   = t0 >> 10;
    const int hw0 = t0 & 1023;

    const float* xb = x + (size_t)n * (CC * HW) + hw0;

    // loader roles
    const int kX  = tid >> 5;           // 0..15
    const int jX  = (tid & 31) << 2;
    const int mmW = tid >> 2;           // 0..127
    const int kqW = (tid & 3) << 2;
    const int rowW = m0 + mmW;

    float4 sx, sw;
    sx = *(const float4*)&xb[(size_t)kX * HW + jX];
    sw = (rowW < MM) ? *(const float4*)&w[rowW * CC + kqW]
                     : make_float4(0.f, 0.f, 0.f, 0.f);

    ull acc[8][2];
    #pragma unroll
    for (int i = 0; i < 8; i++) { acc[i][0] = 0ull; acc[i][1] = 0ull; }

    #pragma unroll 1
    for (int ci = 0; ci < 16; ci++) {
        const int buf = ci & 1;
        // commit staged chunk ci into buffer buf.
        // Safe: slowest coexisting warps are in compute(ci-1) reading buf^1;
        // last readers of THIS buf (compute ci-2) are behind barrier(ci-1).
        *(float4*)&Xs[buf][kX][jX] = sx;
        Ws[buf][kqW + 0][mmW] = sw.x;
        Ws[buf][kqW + 1][mmW] = sw.y;
        Ws[buf][kqW + 2][mmW] = sw.z;
        Ws[buf][kqW + 3][mmW] = sw.w;

        // stage chunk ci+1 (gmem latency hidden behind barrier + compute)
        if (ci < 15) {
            int c1 = (ci + 1) * 16;
            sx = *(const float4*)&xb[(size_t)(c1 + kX) * HW + jX];
            if (rowW < MM) sw = *(const float4*)&w[rowW * CC + c1 + kqW];
        }

        __syncthreads();

        // compute chunk ci from buffer buf (numerics bit-exact vs R8)
        ull cacc[8][2];
        #pragma unroll
        for (int i = 0; i < 8; i++) { cacc[i][0] = 0ull; cacc[i][1] = 0ull; }

        #pragma unroll
        for (int k = 0; k < 16; k++) {
            ulonglong2 xa = *(const ulonglong2*)&Xs[buf][k][tx * 4]; // 4 toks
            float4 b0 = *(const float4*)&Ws[buf][k][ty * 8];
            float4 b1 = *(const float4*)&Ws[buf][k][ty * 8 + 4];
            float bv[8] = { b0.x, b0.y, b0.z, b0.w, b1.x, b1.y, b1.z, b1.w };
            #pragma unroll
            for (int mi = 0; mi < 8; mi++) {
                ull bb = pk2(bv[mi], bv[mi]);
                cacc[mi][0] = fma2(bb, xa.x, cacc[mi][0]);
                cacc[mi][1] = fma2(bb, xa.y, cacc[mi][1]);
            }
        }

        #pragma unroll
        for (int mi = 0; mi < 8; mi++) {
            acc[mi][0] = add2(acc[mi][0], cacc[mi][0]);
            acc[mi][1] = add2(acc[mi][1], cacc[mi][1]);
        }
    }

    // write logits: att[n][m][hw0 + tx*4 .. +4], coalesced STG.128
    float* ob = att + (size_t)n * ((size_t)MM * HW) + hw0 + tx * 4;
    #pragma unroll
    for (int mi = 0; mi < 8; mi++) {
        int row = m0 + ty * 8 + mi;
        if (row < MM) {
            float4 o;
            upk2(acc[mi][0], o.x, o.y);
            upk2(acc[mi][1], o.z, o.w);
            *(float4*)&ob[(size_t)row * HW] = o;
        }
    }
}

// ============================================================================
// K2': fused softmax + hard-shrink + L1-normalize + sparse y = att @ W.
// (R9 version verbatim — proven 201us.) 4 threads/token; block = 32 tokens
// x 4 groups; all att traffic warp-coalesced. Per-element chains preserved.
// ============================================================================
__global__ __launch_bounds__(128) void softmax_fused_kernel(
    float* __restrict__ att, const float* __restrict__ w,
    float* __restrict__ y)
{
    __shared__ double zs[GQ][32];
    __shared__ float  nzvS[GQ][32][SEGCAP];
    __shared__ int    nzmS[GQ][32][SEGCAP];
    __shared__ int    cntS[GQ][32];

    const int tid  = threadIdx.x;
    const int q    = tid >> 5;          // segment 0..3
    const int lane = tid & 31;          // token within block
    const int t    = blockIdx.x * 32 + lane;
    const int n    = t >> 10;
    const int hw   = t & 1023;
    float* a = att + (size_t)n * ((size_t)MM * HW) + hw;
    const int mlo = q * MSEG;

    // ---- pass A: partial Z over this segment ----
    double z = 0.0;
    for (int m = mlo; m < mlo + 496; m += 16) {
        float v[16];
        #pragma unroll
        for (int i = 0; i < 16; i++) v[i] = a[(size_t)(m + i) << 10];
        float e[16];
        #pragma unroll
        for (int i = 0; i < 16; i++) e[i] = exp_acc(v[i]);
        #pragma unroll
        for (int g = 0; g < 2; g++) {
            const float* eg = e + g * 8;
            float s01 = __fadd_rn(eg[0], eg[1]);
            float s23 = __fadd_rn(eg[2], eg[3]);
            float s45 = __fadd_rn(eg[4], eg[5]);
            float s67 = __fadd_rn(eg[6], eg[7]);
            float s03 = __fadd_rn(s01, s23);
            float s47 = __fadd_rn(s45, s67);
            z += (double)__fadd_rn(s03, s47);
        }
    }
    {   // remainder 4
        int m = mlo + 496;
        float v[4], e[4];
        #pragma unroll
        for (int i = 0; i < 4; i++) v[i] = a[(size_t)(m + i) << 10];
        #pragma unroll
        for (int i = 0; i < 4; i++) e[i] = exp_acc(v[i]);
        float s01 = __fadd_rn(e[0], e[1]);
        float s23 = __fadd_rn(e[2], e[3]);
        z += (double)__fadd_rn(s01, s23);
    }
    zs[q][lane] = z;
    __syncthreads();
    const double zt = ((zs[0][lane] + zs[1][lane]) + zs[2][lane]) + zs[3][lane];
    const float invZ = __fdiv_rn(1.0f, (float)zt);

    // ---- pass B: threshold, record nonzeros, zero this segment ----
    int   lm[SEGCAP];
    float lv[SEGCAP];
    int   cnt = 0;
    for (int m = mlo; m < mlo + MSEG; m += 4) {
        float v[4];
        #pragma unroll
        for (int i = 0; i < 4; i++) v[i] = a[(size_t)(m + i) << 10];
        #pragma unroll
        for (int i = 0; i < 4; i++) {
            float e = exp_acc(v[i]);
            float p = __fmul_rn(e, invZ);
            float d = __fadd_rn(p, -LAMBDA);
            float val;
            if (fabsf(d) < 2.5e-6f) {
                // near the discontinuity: decide membership in fp64
                double p64 = exp((double)v[i]) / zt;
                if (p64 > (double)LAMBDA) {
                    if (d > 0.f)
                        val = __fdiv_rn(__fmul_rn(d, p), __fadd_rn(d, EPSN));
                    else
                        val = p;
                } else {
                    val = 0.f;
                }
            } else {
                val = (d > 0.f) ? p : 0.f;
            }
            if (val != 0.f && cnt < SEGCAP) { lm[cnt] = m + i; lv[cnt] = val; cnt++; }
        }
        #pragma unroll
        for (int i = 0; i < 4; i++) a[(size_t)(m + i) << 10] = 0.f;
    }
    cntS[q][lane] = cnt;
    for (int k = 0; k < cnt; k++) {
        nzmS[q][lane][k] = lm[k];
        nzvS[q][lane][k] = lv[k];
    }
    __syncthreads();

    // ---- S over merged list (ascending m) ----
    float s = 0.f;
    #pragma unroll
    for (int qq = 0; qq < GQ; qq++) {
        int c = cntS[qq][lane];
        for (int k = 0; k < c; k++)
            s = __fadd_rn(s, nzvS[qq][lane][k]);
    }
    const float invS = __fdiv_rn(1.0f, fmaxf(s, 1e-12f));

    // ---- scatter this segment's normalized nonzeros ----
    for (int k = 0; k < cnt; k++)
        a[(size_t)lm[k] << 10] = __fmul_rn(lv[k], invS);

    // ---- y: this thread does c in [q*64, q*64+64), two blocks of 32 ----
    float* yb = y + (size_t)n * (CC * HW) + hw;
    #pragma unroll 1
    for (int cb = 0; cb < 2; cb++) {
        const int c0 = q * 64 + cb * 32;
        float accy[32];
        #pragma unroll
        for (int c = 0; c < 32; c++) accy[c] = 0.f;
        #pragma unroll 1
        for (int qq = 0; qq < GQ; qq++) {
            int c = cntS[qq][lane];
            for (int k = 0; k < c; k++) {
                float vn = __fmul_rn(nzvS[qq][lane][k], invS);
                const float4* wr4 =
                    (const float4*)(w + nzmS[qq][lane][k] * CC + c0);
                #pragma unroll
                for (int j = 0; j < 8; j++) {
                    float4 wv = wr4[j];
                    accy[j*4+0] = fmaf(vn, wv.x, accy[j*4+0]);
                    accy[j*4+1] = fmaf(vn, wv.y, accy[j*4+1]);
                    accy[j*4+2] = fmaf(vn, wv.z, accy[j*4+2]);
                    accy[j*4+3] = fmaf(vn, wv.w, accy[j*4+3]);
                }
            }
        }
        #pragma unroll
        for (int c = 0; c < 32; c++)
            yb[(size_t)(c0 + c) * HW] = accy[c];
    }
}

// ============================================================================
extern "C" void kernel_launch(void* const* d_in, const int* in_sizes, int n_in,
                              void* d_out, int out_size)
{
    const float* x = (const float*)d_in[0];   // (32,256,32,32)
    const float* w = (const float*)d_in[1];   // (2000,256)
    float* y   = (float*)d_out;               // first 8,388,608 floats
    float* att = y + Y_ELEMS;                 // next 65,536,000 floats

    dim3 g1((MM + 127) / 128, TT / 128);      // (16, 256)
    gemm1_kernel<<<g1, 512>>>(x, w, att);

    softmax_fused_kernel<<<TT / 32, 128>>>(att, w, y);
}

// round 13
// speedup vs baseline: 1.5169x; 1.0355x over previous
#include <cuda_runtime.h>
#include <cuda_bf16.h>

// MemModule: x(32,256,32,32) fp32, weight(2000,256) fp32
//   att = L1norm(hardshrink(softmax(xT @ W^T)))   -> (32,2000,32,32)
//   y   = att @ W                                  -> (32,256,32,32)
// d_out layout: [ y (8,388,608 floats) | att (65,536,000 floats) ]
// att region doubles as logit scratch.
// R13: K1 keeps R12's double-buffer/single-barrier pipeline but swaps the
// broadcast roles in the micro-kernel: x is broadcast (4 pk2/k, was 8) and
// W comes as natural (m,m+1) f32x2 pairs via broadcast LDS.128 from the SAME
// Ws layout (no extra crossbar). Per-lane scalar chains unchanged -> logits
// BIT-IDENTICAL. Fused kernel: pass B widened to m-step 8 (MLP), chains
// unchanged.

#define NB   32
#define CC   256
#define HW   1024           // 32*32
#define TT   32768          // NB*HW tokens
#define MM   2000
#define Y_ELEMS  (NB*CC*HW) // 8388608
#define LAMBDA 0.0025f
#define EPSN   1e-12f
#define GQ    4             // m-split groups per token
#define MSEG  500           // MM / GQ
#define SEGCAP 16           // nz capacity per segment

typedef unsigned long long ull;

// ---------- packed f32x2 helpers ----------
__device__ __forceinline__ ull pk2(float lo, float hi) {
    ull r;
    asm("mov.b64 %0, {%1,%2};" : "=l"(r) : "f"(lo), "f"(hi));
    return r;
}
__device__ __forceinline__ void upk2(ull v, float& lo, float& hi) {
    asm("mov.b64 {%0,%1}, %2;" : "=f"(lo), "=f"(hi) : "l"(v));
}
__device__ __forceinline__ ull fma2(ull a, ull b, ull c) {
    ull d;
    asm("fma.rn.f32x2 %0, %1, %2, %3;" : "=l"(d) : "l"(a), "l"(b), "l"(c));
    return d;
}
__device__ __forceinline__ ull add2(ull a, ull b) {
    ull d;
    asm("add.rn.f32x2 %0, %1, %2;" : "=l"(d) : "l"(a), "l"(b));
    return d;
}

// ---------- accurate expf (~2 ulp), immune to fast-math ----------
__device__ __forceinline__ float exp_acc(float x) {
    float kf = fmaf(x, 1.44269504088896341f, 12582912.0f);
    kf = __fadd_rn(kf, -12582912.0f);
    float r = fmaf(kf, -0.693359375f, x);
    r = fmaf(kf, 2.12194440e-4f, r);
    float p =         1.9875691500e-4f;
    p = fmaf(p, r,    1.3981999507e-3f);
    p = fmaf(p, r,    8.3334519073e-3f);
    p = fmaf(p, r,    4.1665795894e-2f);
    p = fmaf(p, r,    1.6666665459e-1f);
    p = fmaf(p, r,    5.0000001201e-1f);
    float z2 = __fmul_rn(r, r);
    float y = fmaf(p, z2, r);
    y = __fadd_rn(y, 1.0f);
    int ki = (int)kf;
    return __fmul_rn(y, __int_as_float((ki + 127) << 23));
}

// ============================================================================
// K1: logits[t][m] = sum_c x_t[t][c] * w[m][c]  -> att region (n,m,hw) layout.
// 512 threads, tile 128 tok x 128 m, micro 4tok x 8m, double-buffered smem
// with ONE barrier per chunk. Micro-kernel: x broadcast via pk2 (4/k), W as
// natural (m,m+1) f32x2 pairs via 2 broadcast LDS.128. Per-lane scalar fma
// chain (operands + order) BIT-IDENTICAL to R12.
// ============================================================================
__global__ __launch_bounds__(512) void gemm1_kernel(
    const float* __restrict__ x, const float* __restrict__ w,
    float* __restrict__ att)
{
    __shared__ float Xs[2][16][128];
    __shared__ float Ws[2][16][132];   // +4 pad, [k][m] transposed

    const int tid = threadIdx.x;
    const int tx  = tid & 31;       // token group (4 toks)
    const int ty  = tid >> 5;       // m group (8 m), 0..15
    const int m0  = blockIdx.x * 128;
    const int t0  = blockIdx.y * 128;
    const int n   = t0 >> 10;
    const int hw0 = t0 & 1023;

    const float* xb = x + (size_t)n * (CC * HW) + hw0;

    // loader roles
    const int kX  = tid >> 5;           // 0..15
    const int jX  = (tid & 31) << 2;
    const int mmW = tid >> 2;           // 0..127
    const int kqW = (tid & 3) << 2;
    const int rowW = m0 + mmW;

    float4 sx, sw;
    sx = *(const float4*)&xb[(size_t)kX * HW + jX];
    sw = (rowW < MM) ? *(const float4*)&w[rowW * CC + kqW]
                     : make_float4(0.f, 0.f, 0.f, 0.f);

    // acc[j][q]: token j (tx*4+j), m-pair q -> (m0+ty*8+2q, +2q+1)
    ull acc[4][4];
    #pragma unroll
    for (int i = 0; i < 4; i++)
        #pragma unroll
        for (int j = 0; j < 4; j++) acc[i][j] = 0ull;

    #pragma unroll 1
    for (int ci = 0; ci < 16; ci++) {
        const int buf = ci & 1;
        // commit staged chunk ci into buffer buf (safe: last readers of this
        // buf are behind barrier ci-1).
        *(float4*)&Xs[buf][kX][jX] = sx;
        Ws[buf][kqW + 0][mmW] = sw.x;
        Ws[buf][kqW + 1][mmW] = sw.y;
        Ws[buf][kqW + 2][mmW] = sw.z;
        Ws[buf][kqW + 3][mmW] = sw.w;

        // stage chunk ci+1 (gmem latency hidden behind barrier + compute)
        if (ci < 15) {
            int c1 = (ci + 1) * 16;
            sx = *(const float4*)&xb[(size_t)(c1 + kX) * HW + jX];
            if (rowW < MM) sw = *(const float4*)&w[rowW * CC + c1 + kqW];
        }

        __syncthreads();

        // compute chunk ci from buffer buf (per-lane numerics == R12)
        ull cacc[4][4];
        #pragma unroll
        for (int i = 0; i < 4; i++)
            #pragma unroll
            for (int j = 0; j < 4; j++) cacc[i][j] = 0ull;

        #pragma unroll
        for (int k = 0; k < 16; k++) {
            float4 xa = *(const float4*)&Xs[buf][k][tx * 4];     // 4 toks
            // 8 m as 4 natural f32x2 pairs: 2 broadcast LDS.128
            ulonglong2 wp0 = *(const ulonglong2*)&Ws[buf][k][ty * 8];
            ulonglong2 wp1 = *(const ulonglong2*)&Ws[buf][k][ty * 8 + 4];
            ull xj0 = pk2(xa.x, xa.x);
            ull xj1 = pk2(xa.y, xa.y);
            ull xj2 = pk2(xa.z, xa.z);
            ull xj3 = pk2(xa.w, xa.w);
            cacc[0][0] = fma2(xj0, wp0.x, cacc[0][0]);
            cacc[0][1] = fma2(xj0, wp0.y, cacc[0][1]);
            cacc[0][2] = fma2(xj0, wp1.x, cacc[0][2]);
            cacc[0][3] = fma2(xj0, wp1.y, cacc[0][3]);
            cacc[1][0] = fma2(xj1, wp0.x, cacc[1][0]);
            cacc[1][1] = fma2(xj1, wp0.y, cacc[1][1]);
            cacc[1][2] = fma2(xj1, wp1.x, cacc[1][2]);
            cacc[1][3] = fma2(xj1, wp1.y, cacc[1][3]);
            cacc[2][0] = fma2(xj2, wp0.x, cacc[2][0]);
            cacc[2][1] = fma2(xj2, wp0.y, cacc[2][1]);
            cacc[2][2] = fma2(xj2, wp1.x, cacc[2][2]);
            cacc[2][3] = fma2(xj2, wp1.y, cacc[2][3]);
            cacc[3][0] = fma2(xj3, wp0.x, cacc[3][0]);
            cacc[3][1] = fma2(xj3, wp0.y, cacc[3][1]);
            cacc[3][2] = fma2(xj3, wp1.x, cacc[3][2]);
            cacc[3][3] = fma2(xj3, wp1.y, cacc[3][3]);
        }

        #pragma unroll
        for (int i = 0; i < 4; i++)
            #pragma unroll
            for (int j = 0; j < 4; j++)
                acc[i][j] = add2(acc[i][j], cacc[i][j]);
    }

    // write logits: regroup acc into float4 per m-row, coalesced STG.128.
    // For m = ty*8 + mi: value for token j is component (mi&1) of acc[j][mi>>1].
    float* ob = att + (size_t)n * ((size_t)MM * HW) + hw0 + tx * 4;
    #pragma unroll
    for (int mi = 0; mi < 8; mi++) {
        int row = m0 + ty * 8 + mi;
        if (row < MM) {
            const int q = mi >> 1;
            float4 o;
            float lo, hi;
            upk2(acc[0][q], lo, hi); o.x = (mi & 1) ? hi : lo;
            upk2(acc[1][q], lo, hi); o.y = (mi & 1) ? hi : lo;
            upk2(acc[2][q], lo, hi); o.z = (mi & 1) ? hi : lo;
            upk2(acc[3][q], lo, hi); o.w = (mi & 1) ? hi : lo;
            *(float4*)&ob[(size_t)row * HW] = o;
        }
    }
}

// ============================================================================
// K2': fused softmax + hard-shrink + L1-normalize + sparse y = att @ W.
// 4 threads/token; block = 32 tokens x 4 groups; att traffic warp-coalesced.
// Pass B widened to m-step 8 (up-front loads, ascending order preserved).
// All per-element chains identical to R12.
// ============================================================================
__global__ __launch_bounds__(128) void softmax_fused_kernel(
    float* __restrict__ att, const float* __restrict__ w,
    float* __restrict__ y)
{
    __shared__ double zs[GQ][32];
    __shared__ float  nzvS[GQ][32][SEGCAP];
    __shared__ int    nzmS[GQ][32][SEGCAP];
    __shared__ int    cntS[GQ][32];

    const int tid  = threadIdx.x;
    const int q    = tid >> 5;          // segment 0..3
    const int lane = tid & 31;          // token within block
    const int t    = blockIdx.x * 32 + lane;
    const int n    = t >> 10;
    const int hw   = t & 1023;
    float* a = att + (size_t)n * ((size_t)MM * HW) + hw;
    const int mlo = q * MSEG;

    // ---- pass A: partial Z over this segment ----
    double z = 0.0;
    for (int m = mlo; m < mlo + 496; m += 16) {
        float v[16];
        #pragma unroll
        for (int i = 0; i < 16; i++) v[i] = a[(size_t)(m + i) << 10];
        float e[16];
        #pragma unroll
        for (int i = 0; i < 16; i++) e[i] = exp_acc(v[i]);
        #pragma unroll
        for (int g = 0; g < 2; g++) {
            const float* eg = e + g * 8;
            float s01 = __fadd_rn(eg[0], eg[1]);
            float s23 = __fadd_rn(eg[2], eg[3]);
            float s45 = __fadd_rn(eg[4], eg[5]);
            float s67 = __fadd_rn(eg[6], eg[7]);
            float s03 = __fadd_rn(s01, s23);
            float s47 = __fadd_rn(s45, s67);
            z += (double)__fadd_rn(s03, s47);
        }
    }
    {   // remainder 4
        int m = mlo + 496;
        float v[4], e[4];
        #pragma unroll
        for (int i = 0; i < 4; i++) v[i] = a[(size_t)(m + i) << 10];
        #pragma unroll
        for (int i = 0; i < 4; i++) e[i] = exp_acc(v[i]);
        float s01 = __fadd_rn(e[0], e[1]);
        float s23 = __fadd_rn(e[2], e[3]);
        z += (double)__fadd_rn(s01, s23);
    }
    zs[q][lane] = z;
    __syncthreads();
    const double zt = ((zs[0][lane] + zs[1][lane]) + zs[2][lane]) + zs[3][lane];
    const float invZ = __fdiv_rn(1.0f, (float)zt);

    // ---- pass B: threshold, record nonzeros, zero this segment ----
    int   lm[SEGCAP];
    float lv[SEGCAP];
    int   cnt = 0;
    for (int m = mlo; m < mlo + 496; m += 8) {
        float v[8];
        #pragma unroll
        for (int i = 0; i < 8; i++) v[i] = a[(size_t)(m + i) << 10];
        #pragma unroll
        for (int i = 0; i < 8; i++) {
            float e = exp_acc(v[i]);
            float p = __fmul_rn(e, invZ);
            float d = __fadd_rn(p, -LAMBDA);
            float val;
            if (fabsf(d) < 2.5e-6f) {
                // near the discontinuity: decide membership in fp64
                double p64 = exp((double)v[i]) / zt;
                if (p64 > (double)LAMBDA) {
                    if (d > 0.f)
                        val = __fdiv_rn(__fmul_rn(d, p), __fadd_rn(d, EPSN));
                    else
                        val = p;
                } else {
                    val = 0.f;
                }
            } else {
                val = (d > 0.f) ? p : 0.f;
            }
            if (val != 0.f && cnt < SEGCAP) { lm[cnt] = m + i; lv[cnt] = val; cnt++; }
        }
        #pragma unroll
        for (int i = 0; i < 8; i++) a[(size_t)(m + i) << 10] = 0.f;
    }
    {   // remainder 4
        int m = mlo + 496;
        float v[4];
        #pragma unroll
        for (int i = 0; i < 4; i++) v[i] = a[(size_t)(m + i) << 10];
        #pragma unroll
        for (int i = 0; i < 4; i++) {
            float e = exp_acc(v[i]);
            float p = __fmul_rn(e, invZ);
            float d = __fadd_rn(p, -LAMBDA);
            float val;
            if (fabsf(d) < 2.5e-6f) {
                double p64 = exp((double)v[i]) / zt;
                if (p64 > (double)LAMBDA) {
                    if (d > 0.f)
                        val = __fdiv_rn(__fmul_rn(d, p), __fadd_rn(d, EPSN));
                    else
                        val = p;
                } else {
                    val = 0.f;
                }
            } else {
                val = (d > 0.f) ? p : 0.f;
            }
            if (val != 0.f && cnt < SEGCAP) { lm[cnt] = m + i; lv[cnt] = val; cnt++; }
        }
        #pragma unroll
        for (int i = 0; i < 4; i++) a[(size_t)(m + i) << 10] = 0.f;
    }
    cntS[q][lane] = cnt;
    for (int k = 0; k < cnt; k++) {
        nzmS[q][lane][k] = lm[k];
        nzvS[q][lane][k] = lv[k];
    }
    __syncthreads();

    // ---- S over merged list (ascending m) ----
    float s = 0.f;
    #pragma unroll
    for (int qq = 0; qq < GQ; qq++) {
        int c = cntS[qq][lane];
        for (int k = 0; k < c; k++)
            s = __fadd_rn(s, nzvS[qq][lane][k]);
    }
    const float invS = __fdiv_rn(1.0f, fmaxf(s, 1e-12f));

    // ---- scatter this segment's normalized nonzeros ----
    for (int k = 0; k < cnt; k++)
        a[(size_t)lm[k] << 10] = __fmul_rn(lv[k], invS);

    // ---- y: this thread does c in [q*64, q*64+64), two blocks of 32 ----
    float* yb = y + (size_t)n * (CC * HW) + hw;
    #pragma unroll 1
    for (int cb = 0; cb < 2; cb++) {
        const int c0 = q * 64 + cb * 32;
        float accy[32];
        #pragma unroll
        for (int c = 0; c < 32; c++) accy[c] = 0.f;
        #pragma unroll 1
        for (int qq = 0; qq < GQ; qq++) {
            int c = cntS[qq][lane];
            for (int k = 0; k < c; k++) {
                float vn = __fmul_rn(nzvS[qq][lane][k], invS);
                const float4* wr4 =
                    (const float4*)(w + nzmS[qq][lane][k] * CC + c0);
                #pragma unroll
                for (int j = 0; j < 8; j++) {
                    float4 wv = wr4[j];
                    accy[j*4+0] = fmaf(vn, wv.x, accy[j*4+0]);
                    accy[j*4+1] = fmaf(vn, wv.y, accy[j*4+1]);
                    accy[j*4+2] = fmaf(vn, wv.z, accy[j*4+2]);
                    accy[j*4+3] = fmaf(vn, wv.w, accy[j*4+3]);
                }
            }
        }
        #pragma unroll
        for (int c = 0; c < 32; c++)
            yb[(size_t)(c0 + c) * HW] = accy[c];
    }
}

// ============================================================================
extern "C" void kernel_launch(void* const* d_in, const int* in_sizes, int n_in,
                              void* d_out, int out_size)
{
    const float* x = (const float*)d_in[0];   // (32,256,32,32)
    const float* w = (const float*)d_in[1];   // (2000,256)
    float* y   = (float*)d_out;               // first 8,388,608 floats
    float* att = y + Y_ELEMS;                 // next 65,536,000 floats

    dim3 g1((MM + 127) / 128, TT / 128);      // (16, 256)
    gemm1_kernel<<<g1, 512>>>(x, w, att);

    softmax_fused_kernel<<<TT / 32, 128>>>(att, w, y);
}